// round 17
// baseline (speedup 1.0000x reference)
#include <cuda_runtime.h>
#include <cstdint>

#define L1LEN 512
#define L2LEN 512
#define DDIM  256
#define BATCH 2
#define NG    16
#define GS    16
#define TI    8
#define TJ    32
#define JSPLIT 2
#define NHALF (L2LEN / JSPLIT / TJ)
#define KSTR  260
#define NSTR  20
#define NTHR  256

__device__ float g_Q[BATCH * L1LEN * DDIM];
__device__ float g_K[BATCH * L2LEN * DDIM];
__device__ float g_V[BATCH * L2LEN * DDIM];
__device__ float g_pacc[BATCH * 64 * JSPLIT * TI * DDIM];
__device__ float g_pl[BATCH * 64 * JSPLIT * TI * NG];

// tf32 hi/lo planes (prep kernel output)
__device__ uint32_t g_xt_hi[BATCH * L1LEN * DDIM];
__device__ uint32_t g_xt_lo[BATCH * L1LEN * DDIM];
__device__ uint32_t g_xs_hi[BATCH * L2LEN * DDIM];
__device__ uint32_t g_xs_lo[BATCH * L2LEN * DDIM];
__device__ uint32_t g_W_hi[3][DDIM * DDIM];
__device__ uint32_t g_W_lo[3][DDIM * DDIM];

// ---------------------------------------------------------------------------
// helpers
// ---------------------------------------------------------------------------
__device__ __forceinline__ uint32_t f2tf32(float f) {
    uint32_t r;
    asm("cvt.rna.tf32.f32 %0, %1;" : "=r"(r) : "f"(f));
    return r;
}

__device__ __forceinline__ void mma_tf32(float* c, const uint32_t* a,
                                         uint32_t b0, uint32_t b1) {
    asm("mma.sync.aligned.m16n8k8.row.col.f32.tf32.tf32.f32 "
        "{%0,%1,%2,%3}, {%4,%5,%6,%7}, {%8,%9}, {%0,%1,%2,%3};"
        : "+f"(c[0]), "+f"(c[1]), "+f"(c[2]), "+f"(c[3])
        : "r"(a[0]), "r"(a[1]), "r"(a[2]), "r"(a[3]), "r"(b0), "r"(b1));
}

__device__ __forceinline__ unsigned long long fma2u(unsigned long long a,
                                                    unsigned long long b,
                                                    unsigned long long c) {
    unsigned long long r;
    asm("fma.rn.f32x2 %0, %1, %2, %3;" : "=l"(r) : "l"(a), "l"(b), "l"(c));
    return r;
}

__device__ __forceinline__ void relu_fma(unsigned long long& acc,
                                         unsigned long long q2,
                                         unsigned long long nk2,
                                         unsigned long long w2) {
    asm("{\n\t"
        ".reg .b64 d;\n\t"
        ".reg .f32 lo, hi;\n\t"
        "add.rn.f32x2 d, %1, %2;\n\t"
        "mov.b64 {lo, hi}, d;\n\t"
        "max.f32 lo, lo, 0f00000000;\n\t"
        "max.f32 hi, hi, 0f00000000;\n\t"
        "mov.b64 d, {lo, hi};\n\t"
        "fma.rn.f32x2 %0, d, %3, %0;\n\t"
        "}"
        : "+l"(acc) : "l"(q2), "l"(nk2), "l"(w2));
}

__device__ __forceinline__ unsigned long long pk2(float a, float b) {
    unsigned long long r;
    asm("mov.b64 %0, {%1, %2};" : "=l"(r) : "f"(a), "f"(b));
    return r;
}

__device__ __forceinline__ float2 upk2(unsigned long long v) {
    float2 r;
    asm("mov.b64 {%0, %1}, %2;" : "=f"(r.x), "=f"(r.y) : "l"(v));
    return r;
}

__device__ __forceinline__ void cp16(uint32_t dst, const void* src) {
    asm volatile("cp.async.cg.shared.global [%0], [%1], 16;"
                 :: "r"(dst), "l"(src));
}
__device__ __forceinline__ void cp_commit() {
    asm volatile("cp.async.commit_group;");
}
__device__ __forceinline__ void cp_wait0() {
    asm volatile("cp.async.wait_group 0;");
}

// ---------------------------------------------------------------------------
// Prep: fp32 -> tf32 hi/lo planes. Grid (256, 5), 256 threads.
// ---------------------------------------------------------------------------
__global__ __launch_bounds__(256) void prep_kernel(const float* __restrict__ x_target,
                                                   const float* __restrict__ x_source,
                                                   const float* __restrict__ Wq,
                                                   const float* __restrict__ Wk,
                                                   const float* __restrict__ Wv) {
    const int y = blockIdx.y;
    const float* src;
    uint32_t *hi, *lo;
    int n4;
    if (y == 0)      { src = x_target; hi = g_xt_hi; lo = g_xt_lo; n4 = BATCH * L1LEN * DDIM / 4; }
    else if (y == 1) { src = x_source; hi = g_xs_hi; lo = g_xs_lo; n4 = BATCH * L2LEN * DDIM / 4; }
    else             { src = (y == 2) ? Wq : ((y == 3) ? Wk : Wv);
                       hi = g_W_hi[y - 2]; lo = g_W_lo[y - 2]; n4 = DDIM * DDIM / 4; }
    int idx = blockIdx.x * 256 + threadIdx.x;
    if (idx >= n4) return;
    float4 v = *(const float4*)&src[idx * 4];
    uint32_t h0 = f2tf32(v.x), h1 = f2tf32(v.y);
    uint32_t h2 = f2tf32(v.z), h3 = f2tf32(v.w);
    uint4 hv = make_uint4(h0, h1, h2, h3);
    uint4 lv = make_uint4(f2tf32(v.x - __uint_as_float(h0)),
                          f2tf32(v.y - __uint_as_float(h1)),
                          f2tf32(v.z - __uint_as_float(h2)),
                          f2tf32(v.w - __uint_as_float(h3)));
    *(uint4*)&hi[idx * 4] = hv;
    *(uint4*)&lo[idx * 4] = lv;
}

// ---------------------------------------------------------------------------
// QKV GEMM: pure tensor-core loop, cp.async double-buffered hi/lo planes.
// 128 threads, tile 64x32, grid (16,8,3)=384. DYNAMIC smem (55.3KB > 48KB static).
// Layout (uint32): xsh 2*64*36 | xsl 2*64*36 | wsh 2*32*36 | wsl 2*32*36
// ---------------------------------------------------------------------------
#define QXS(buf, r, c)  dsm[(buf) * 2304 + (r) * 36 + (c)]
#define QXL(buf, r, c)  dsm[4608 + (buf) * 2304 + (r) * 36 + (c)]
#define QWH(buf, r, c)  dsm[9216 + (buf) * 1152 + (r) * 36 + (c)]
#define QWL(buf, r, c)  dsm[11520 + (buf) * 1152 + (r) * 36 + (c)]
#define QKV_SMEM_BYTES  (13824 * 4)

__global__ __launch_bounds__(128) void qkv_gemm() {
    extern __shared__ uint32_t dsm[];
    const int z = blockIdx.z;
    const uint32_t* __restrict__ xhi = (z == 0) ? g_xt_hi : g_xs_hi;
    const uint32_t* __restrict__ xlo = (z == 0) ? g_xt_lo : g_xs_lo;
    const uint32_t* __restrict__ whi = g_W_hi[z];
    const uint32_t* __restrict__ wlo = g_W_lo[z];
    float* __restrict__ y = (z == 0) ? g_Q : ((z == 1) ? g_K : g_V);

    const int t    = threadIdx.x;
    const int warp = t >> 5;
    const int lane = t & 31;
    const int gid  = lane >> 2;
    const int tig  = lane & 3;
    const int m_blk = blockIdx.x * 64;
    const int n_blk = blockIdx.y * 32;

    float acc[4][4] = {};

#define QLOAD(buf, kc)                                                         \
    {                                                                          \
        uint32_t dxh = (uint32_t)__cvta_generic_to_shared(&QXS(buf, 0, 0));    \
        uint32_t dxl = (uint32_t)__cvta_generic_to_shared(&QXL(buf, 0, 0));    \
        uint32_t dwh = (uint32_t)__cvta_generic_to_shared(&QWH(buf, 0, 0));    \
        uint32_t dwl = (uint32_t)__cvta_generic_to_shared(&QWL(buf, 0, 0));    \
        _Pragma("unroll")                                                      \
        for (int i = 0; i < 4; i++) {                                          \
            int idx = t + i * 128;                                             \
            int row = idx >> 3, col = (idx & 7) * 4;                           \
            int so = (row * 36 + col) * 4;                                     \
            int go = (m_blk + row) * DDIM + (kc) + col;                        \
            cp16(dxh + so, &xhi[go]);                                          \
            cp16(dxl + so, &xlo[go]);                                          \
        }                                                                      \
        _Pragma("unroll")                                                      \
        for (int i = 0; i < 2; i++) {                                          \
            int idx = t + i * 128;                                             \
            int row = idx >> 3, col = (idx & 7) * 4;                           \
            int so = (row * 36 + col) * 4;                                     \
            int go = (n_blk + row) * DDIM + (kc) + col;                        \
            cp16(dwh + so, &whi[go]);                                          \
            cp16(dwl + so, &wlo[go]);                                          \
        }                                                                      \
        cp_commit();                                                           \
    }

    QLOAD(0, 0);

#pragma unroll
    for (int chunk = 0; chunk < 8; chunk++) {
        const int cur = chunk & 1;
        cp_wait0();
        __syncthreads();
        if (chunk < 7) QLOAD(1 - cur, (chunk + 1) * 32);

#pragma unroll
        for (int ks = 0; ks < 4; ks++) {
            const int k0 = ks * 8;
            uint32_t ahi[4], alo[4];
            ahi[0] = QXS(cur, warp * 16 + gid, k0 + tig);
            ahi[1] = QXS(cur, warp * 16 + gid + 8, k0 + tig);
            ahi[2] = QXS(cur, warp * 16 + gid, k0 + tig + 4);
            ahi[3] = QXS(cur, warp * 16 + gid + 8, k0 + tig + 4);
            alo[0] = QXL(cur, warp * 16 + gid, k0 + tig);
            alo[1] = QXL(cur, warp * 16 + gid + 8, k0 + tig);
            alo[2] = QXL(cur, warp * 16 + gid, k0 + tig + 4);
            alo[3] = QXL(cur, warp * 16 + gid + 8, k0 + tig + 4);
#pragma unroll
            for (int nb = 0; nb < 4; nb++) {
                uint32_t bhi0 = QWH(cur, nb * 8 + gid, k0 + tig);
                uint32_t bhi1 = QWH(cur, nb * 8 + gid, k0 + tig + 4);
                uint32_t blo0 = QWL(cur, nb * 8 + gid, k0 + tig);
                uint32_t blo1 = QWL(cur, nb * 8 + gid, k0 + tig + 4);
                mma_tf32(acc[nb], ahi, bhi0, bhi1);
                mma_tf32(acc[nb], ahi, blo0, blo1);
                mma_tf32(acc[nb], alo, bhi0, bhi1);
            }
        }
        __syncthreads();
    }

    const int m = m_blk + warp * 16 + gid;
#pragma unroll
    for (int nb = 0; nb < 4; nb++) {
        const int n = n_blk + nb * 8 + 2 * tig;
        *(float2*)&y[m * DDIM + n]       = make_float2(acc[nb][0], acc[nb][1]);
        *(float2*)&y[(m + 8) * DDIM + n] = make_float2(acc[nb][2], acc[nb][3]);
    }
}

// ---------------------------------------------------------------------------
// Fused attention (unchanged R15 / 63.5us version).
// ---------------------------------------------------------------------------
__global__ __launch_bounds__(NTHR, 2) void attn_kernel(const float* __restrict__ wmlp,
                                                       const float* __restrict__ bmlp) {
    extern __shared__ float sm[];
    float* q    = sm;
    float* kbuf = q + TI * DDIM;
    float* sc2  = kbuf + 2 * TJ * KSTR;

    const int t     = threadIdx.x;
    const int bx    = blockIdx.x;
    const int b     = bx >> 7;
    const int itile = (bx >> 1) & 63;
    const int jh2   = bx & 1;
    const int i_base = itile * TI;
    const int part   = bx;

    const int jj = t & 31;
    const int nc = t >> 5;
    const int qp = t & 31;
    const int ih = (t >> 5) & 1;
    const int jq = t >> 6;
    const int n0 = (4 * qp) & 15;

    const float b0 = bmlp[0];
    unsigned long long w2[8];
#pragma unroll
    for (int p = 0; p < 8; p++) w2[p] = pk2(wmlp[2 * p], wmlp[2 * p + 1]);

    {
        const float* Qg = g_Q + (b * L1LEN + i_base) * DDIM;
#pragma unroll
        for (int it = 0; it < 2; it++) {
            int idx = t + it * NTHR;
            int row = idx >> 6, col = (idx & 63) * 4;
            *(float4*)&q[row * DDIM + col] = *(const float4*)&Qg[row * DDIM + col];
        }
    }

    const float* Kg = g_K + (b * L2LEN + jh2 * (L2LEN / JSPLIT)) * DDIM;
    const float* Vg = g_V + (b * L2LEN + jh2 * (L2LEN / JSPLIT)) * DDIM;

    {
        uint32_t dst = (uint32_t)__cvta_generic_to_shared(kbuf);
#pragma unroll
        for (int it = 0; it < (TJ * DDIM / 4) / NTHR; it++) {
            int idx = t + it * NTHR;
            int row = idx >> 6, col = (idx & 63) * 4;
            cp16(dst + (row * KSTR + col) * 4, &Kg[row * DDIM + col]);
        }
        cp_commit();
    }

    ulonglong2 acc2[4][2];
#pragma unroll
    for (int r = 0; r < 4; r++) {
        acc2[r][0].x = 0ull; acc2[r][0].y = 0ull;
        acc2[r][1].x = 0ull; acc2[r][1].y = 0ull;
    }
    float lsum = 0.f;

    for (int tile = 0; tile < NHALF; tile++) {
        cp_wait0();
        __syncthreads();

        if (tile + 1 < NHALF) {
            const float* Kn = Kg + (tile + 1) * TJ * DDIM;
            uint32_t dst = (uint32_t)__cvta_generic_to_shared(
                kbuf + ((tile + 1) & 1) * TJ * KSTR);
#pragma unroll
            for (int it = 0; it < (TJ * DDIM / 4) / NTHR; it++) {
                int idx = t + it * NTHR;
                int row = idx >> 6, col = (idx & 63) * 4;
                cp16(dst + (row * KSTR + col) * 4, &Kn[row * DDIM + col]);
            }
            cp_commit();
        }

        const float* kt = kbuf + (tile & 1) * TJ * KSTR;

#pragma unroll
        for (int n2 = 0; n2 < 2; n2++) {
            const int n = nc * 2 + n2;
            const float* kr = kt + jj * KSTR + n * GS;
            unsigned long long nk2[8];
#pragma unroll
            for (int dq = 0; dq < 4; dq++) {
                float4 kq = *(const float4*)&kr[dq * 4];
                nk2[dq * 2]     = pk2(-kq.x, -kq.y);
                nk2[dq * 2 + 1] = pk2(-kq.z, -kq.w);
            }
            unsigned long long s2[8];
#pragma unroll
            for (int i = 0; i < 8; i++) s2[i] = 0ull;
#pragma unroll
            for (int dq = 0; dq < 4; dq++) {
#pragma unroll
                for (int i = 0; i < 8; i++) {
                    const ulonglong2 qv =
                        *(const ulonglong2*)&q[i * DDIM + n * GS + dq * 4];
                    relu_fma(s2[i], qv.x, nk2[dq * 2], w2[dq * 2]);
                    relu_fma(s2[i], qv.y, nk2[dq * 2 + 1], w2[dq * 2 + 1]);
                }
            }
#pragma unroll
            for (int i = 0; i < 8; i++) {
                float2 f = upk2(s2[i]);
                sc2[(i * TJ + jj) * NSTR + n] =
                    __expf(fmaxf(f.x + f.y + b0, 0.f));
            }
        }
        __syncthreads();

        if (t < TI * NG) {
            const int ci = t >> 4, cn = t & 15;
            const float* base = sc2 + ci * TJ * NSTR + cn;
            float s0 = 0.f, s1 = 0.f;
#pragma unroll
            for (int j = 0; j < TJ; j += 2) {
                s0 += base[j * NSTR];
                s1 += base[(j + 1) * NSTR];
            }
            lsum += s0 + s1;
        }

        {
            const int j0 = jq * 8;
            const float* Vt = Vg + tile * TJ * DDIM;
#pragma unroll
            for (int jo = 0; jo < 8; jo++) {
                const int j = j0 + jo;
                const ulonglong2 v0 =
                    *(const ulonglong2*)&Vt[j * DDIM + 4 * qp];
                const ulonglong2 v1 =
                    *(const ulonglong2*)&Vt[j * DDIM + 4 * qp + 128];
#pragma unroll
                for (int r = 0; r < 4; r++) {
                    const ulonglong2 p = *(const ulonglong2*)
                        &sc2[((4 * ih + r) * TJ + j) * NSTR + n0];
                    acc2[r][0].x = fma2u(p.x, v0.x, acc2[r][0].x);
                    acc2[r][0].y = fma2u(p.y, v0.y, acc2[r][0].y);
                    acc2[r][1].x = fma2u(p.x, v1.x, acc2[r][1].x);
                    acc2[r][1].y = fma2u(p.y, v1.y, acc2[r][1].y);
                }
            }
        }
    }

    __syncthreads();
    {
        float* scr = kbuf;
        int base = (t >> 5) * 1024 + qp * 32;
#pragma unroll
        for (int r = 0; r < 4; r++) {
            *(float4*)&scr[base + r * 8]     = *(float4*)&acc2[r][0];
            *(float4*)&scr[base + r * 8 + 4] = *(float4*)&acc2[r][1];
        }
    }
    __syncthreads();
    {
        const int i   = t >> 5;
        const int mih = i >> 2, r = i & 3;
        const float* scr = kbuf;
        float4 s0 = make_float4(0.f, 0.f, 0.f, 0.f);
        float4 s1 = make_float4(0.f, 0.f, 0.f, 0.f);
#pragma unroll
        for (int jqq = 0; jqq < 4; jqq++) {
            const int wv = mih + 2 * jqq;
            const float* pbase = scr + wv * 1024 + (t & 31) * 32 + r * 8;
            float4 a0 = *(const float4*)&pbase[0];
            float4 a1 = *(const float4*)&pbase[4];
            s0.x += a0.x; s0.y += a0.y; s0.z += a0.z; s0.w += a0.w;
            s1.x += a1.x; s1.y += a1.y; s1.z += a1.z; s1.w += a1.w;
        }
        float* pb = g_pacc + part * (TI * DDIM);
        *(float4*)&pb[i * DDIM + 4 * (t & 31)]       = s0;
        *(float4*)&pb[i * DDIM + 4 * (t & 31) + 128] = s1;
    }
    if (t < TI * NG) g_pl[part * (TI * NG) + t] = lsum;
}

// ---------------------------------------------------------------------------
// Merge
// ---------------------------------------------------------------------------
__global__ __launch_bounds__(256) void merge_kernel(float* __restrict__ out) {
    const int bx = blockIdx.x;
    const int t  = threadIdx.x;
    const int p0 = bx * 2, p1 = bx * 2 + 1;
    const float* a0 = g_pacc + p0 * (TI * DDIM);
    const float* a1 = g_pacc + p1 * (TI * DDIM);
    const float* l0 = g_pl + p0 * (TI * NG);
    const float* l1 = g_pl + p1 * (TI * NG);
    float* ob = out + bx * (TI * DDIM);

#pragma unroll
    for (int k = 0; k < 2; k++) {
        int idx = t + k * 256;
        int i   = idx >> 6;
        int d0  = (idx & 63) * 4;
        int nq  = d0 & 15;
        float4 x0 = *(const float4*)&a0[i * DDIM + d0];
        float4 x1 = *(const float4*)&a1[i * DDIM + d0];
        float4 u0 = *(const float4*)&l0[i * NG + nq];
        float4 u1 = *(const float4*)&l1[i * NG + nq];
        float4 r;
        r.x = (x0.x + x1.x) / (u0.x + u1.x);
        r.y = (x0.y + x1.y) / (u0.y + u1.y);
        r.z = (x0.z + x1.z) / (u0.z + u1.z);
        r.w = (x0.w + x1.w) / (u0.w + u1.w);
        *(float4*)&ob[i * DDIM + d0] = r;
    }
}

// ---------------------------------------------------------------------------
extern "C" void kernel_launch(void* const* d_in, const int* in_sizes, int n_in,
                              void* d_out, int out_size) {
    const float* x_source = (const float*)d_in[0];
    const float* x_target = (const float*)d_in[1];
    const float* Wq       = (const float*)d_in[2];
    const float* Wk       = (const float*)d_in[3];
    const float* Wv       = (const float*)d_in[4];
    const float* w_mlp    = (const float*)d_in[5];
    const float* b_mlp    = (const float*)d_in[6];
    float* out            = (float*)d_out;

    prep_kernel<<<dim3(256, 5), 256>>>(x_target, x_source, Wq, Wk, Wv);

    cudaFuncSetAttribute(qkv_gemm, cudaFuncAttributeMaxDynamicSharedMemorySize,
                         QKV_SMEM_BYTES);
    dim3 ggrid(16, 8, 3);
    qkv_gemm<<<ggrid, 128, QKV_SMEM_BYTES>>>();

    const size_t smem_bytes =
        (TI * DDIM + 2 * TJ * KSTR + TI * TJ * NSTR) * sizeof(float);
    cudaFuncSetAttribute(attn_kernel, cudaFuncAttributeMaxDynamicSharedMemorySize,
                         (int)smem_bytes);
    attn_kernel<<<BATCH * 64 * JSPLIT, NTHR, smem_bytes>>>(w_mlp, b_mlp);

    merge_kernel<<<BATCH * 64, 256>>>(out);
}